// round 10
// baseline (speedup 1.0000x reference)
#include <cuda_runtime.h>
#include <cuda_fp16.h>
#include <math.h>

#define NN 50000
#define EE 800000
#define DD 512
#define NHALF 25088   // node split point (multiple of 128)

// ---------------- scratch (device globals; no allocations) ----------------
__device__ __align__(16) __half g_xh[(size_t)NN * DD];    // x in fp16
__device__ __align__(16) __half g_aggh[(size_t)NN * DD];  // aggregated, fp16
__device__ __align__(16) __half g_wh[512 * 512];          // W in fp16
__device__ __align__(16) float g_deg[NN];
__device__ __align__(16) float g_dinv[NN];
__device__ __align__(16) __half g_ew[EE];                 // edge confidence fp16
__device__ __align__(16) unsigned g_rc[EE];               // (col<<16)|row
__device__ int      g_cnt[NN];
__device__ int      g_off[NN];
__device__ int      g_cur[NN];
__device__ unsigned g_epack[EE];      // (ew_fp16 << 16) | src_row
__device__ unsigned g_tstate[128];    // lookback state
__device__ int      g_ticket;
__device__ int      g_idx64;

#define SCAN_B 512
#define NBLK   98

// ---------------- streams/events (created before harness baseline) ---------
static cudaStream_t g_s1;
static cudaEvent_t  g_evFork, g_evConv, g_evFill, g_evAgg0, g_evS1;
static int  g_dev0 = -1;
static bool g_sok = false;
namespace {
struct StreamInit {
    StreamInit() {
        bool ok = cudaStreamCreateWithFlags(&g_s1, cudaStreamNonBlocking) == cudaSuccess;
        ok = ok && cudaEventCreateWithFlags(&g_evFork, cudaEventDisableTiming) == cudaSuccess;
        ok = ok && cudaEventCreateWithFlags(&g_evConv, cudaEventDisableTiming) == cudaSuccess;
        ok = ok && cudaEventCreateWithFlags(&g_evFill, cudaEventDisableTiming) == cudaSuccess;
        ok = ok && cudaEventCreateWithFlags(&g_evAgg0, cudaEventDisableTiming) == cudaSuccess;
        ok = ok && cudaEventCreateWithFlags(&g_evS1,   cudaEventDisableTiming) == cudaSuccess;
        if (ok) cudaGetDevice(&g_dev0);
        g_sok = ok;
    }
};
StreamInit g_streamInit;
}

// ---------------- edge-index dtype-agnostic fetch ----------------
__device__ __forceinline__ long long edge_idx(const void* p, long long i) {
    if (g_idx64) return ((const long long*)p)[i];
    return (long long)((const int*)p)[i];
}

__device__ __forceinline__ uint4 cvt8(float4 f0, float4 f1) {
    uint4 o;
    __half2* oh = (__half2*)&o;
    oh[0] = __float22half2_rn(make_float2(f0.x, f0.y));
    oh[1] = __float22half2_rn(make_float2(f0.z, f0.w));
    oh[2] = __float22half2_rn(make_float2(f1.x, f1.y));
    oh[3] = __float22half2_rn(make_float2(f1.z, f1.w));
    return o;
}

// Convert x and W to fp16 (independent of edge chain).
__global__ void prep_convert(const float* __restrict__ x, const float* __restrict__ W) {
    size_t i = (size_t)blockIdx.x * blockDim.x + threadIdx.x;
    if (i < 512 * 512 / 8)
        ((uint4*)g_wh)[i] = cvt8(((const float4*)W)[i * 2], ((const float4*)W)[i * 2 + 1]);
    if (i < (size_t)NN * DD / 8)
        ((uint4*)g_xh)[i] = cvt8(((const float4*)x)[i * 2], ((const float4*)x)[i * 2 + 1]);
}

// Edge-chain head: detect idx dtype, zero counters and scan state.
__global__ void prep_meta(const void* __restrict__ ei) {
    int i = blockIdx.x * blockDim.x + threadIdx.x;
    if (i == 0) {
        const long long* p = (const long long*)ei;
        int ok = 1;
        for (int j = 0; j < 64; j++) {
            long long v = p[j];
            if (v < 0 || v >= NN) { ok = 0; break; }
        }
        g_idx64 = ok;
        g_ticket = 0;
    }
    if (i < 128) g_tstate[i] = 0;
    if (i < NN) { g_deg[i] = 0.f; g_cnt[i] = 0; }
}

__global__ void edge_pass1(const void* __restrict__ ei,
                           const float* __restrict__ ea,
                           const float* __restrict__ cw,
                           const float* __restrict__ cb) {
    int e = blockIdx.x * blockDim.x + threadIdx.x;
    if (e >= EE) return;
    long long r = edge_idx(ei, e);
    long long c = edge_idx(ei, (long long)EE + e);
    atomicAdd(&g_deg[r], 1.0f);
    atomicAdd(&g_cnt[c], 1);
    g_rc[e] = ((unsigned)c << 16) | (unsigned)r;
    float z = ea[e * 3 + 0] * cw[0] + ea[e * 3 + 1] * cw[1]
            + ea[e * 3 + 2] * cw[2] + cb[0];
    g_ew[e] = __float2half(1.0f / (1.0f + expf(-z)));
}

// Single-launch decoupled-lookback scan; fuses node_dinv + cursor init.
__global__ __launch_bounds__(SCAN_B) void scan_all() {
    __shared__ int s[SCAN_B];
    __shared__ int sbid, sprev;
    const int tid = threadIdx.x;
    if (tid == 0) sbid = atomicAdd(&g_ticket, 1);
    __syncthreads();
    const int bid = sbid;
    const int i = bid * SCAN_B + tid;

    int v = (i < NN) ? g_cnt[i] : 0;
    if (i < NN) {
        float d = g_deg[i];
        g_dinv[i] = (d > 0.f) ? rsqrtf(d) : 0.f;
    }
    s[tid] = v;
    __syncthreads();
    for (int off = 1; off < SCAN_B; off <<= 1) {
        int t = (tid >= off) ? s[tid - off] : 0;
        __syncthreads();
        s[tid] += t;
        __syncthreads();
    }
    const int aggv = s[SCAN_B - 1];

    if (tid == 0) {
        if (bid == 0) {
            atomicExch(&g_tstate[0], (2u << 30) | (unsigned)aggv);
            sprev = 0;
        } else {
            atomicExch(&g_tstate[bid], (1u << 30) | (unsigned)aggv);
            int run = 0;
            for (int t = bid - 1; t >= 0; t--) {
                unsigned st;
                do { st = atomicOr(&g_tstate[t], 0u); } while ((st >> 30) == 0u);
                run += (int)(st & 0x3FFFFFFFu);
                if ((st >> 30) == 2u) break;
            }
            atomicExch(&g_tstate[bid], (2u << 30) | (unsigned)(run + aggv));
            sprev = run;
        }
    }
    __syncthreads();
    if (i < NN) {
        int off = sprev + s[tid] - v;
        g_off[i] = off;
        g_cur[i] = off;
    }
}

// Fill CSR payload from packed rc.
__global__ void fill_kernel() {
    int e = blockIdx.x * blockDim.x + threadIdx.x;
    if (e >= EE) return;
    unsigned rc = g_rc[e];
    unsigned ew = (unsigned)__half_as_ushort(g_ew[e]);
    int p = atomicAdd(&g_cur[rc >> 16], 1);
    g_epack[p] = (ew << 16) | (rc & 0xFFFFu);
}

__device__ __forceinline__ void acc8(float2* acc, uint4 v, float nm) {
    const __half2* h = (const __half2*)&v;
    #pragma unroll
    for (int q = 0; q < 4; q++) {
        float2 f = __half22float2(h[q]);
        acc[q].x += f.x * nm;
        acc[q].y += f.y * nm;
    }
}

// Gather aggregation over node range [n0, n1): one WARP per node.
__global__ __launch_bounds__(256) void agg_kernel(int n0, int n1) {
    int warp = threadIdx.x >> 5;
    int lane = threadIdx.x & 31;
    int n = n0 + blockIdx.x * 8 + warp;
    if (n >= n1) return;
    int start = g_off[n];
    int cnt   = g_cnt[n];
    float dsn = g_dinv[n];

    float2 accA[4] = {{0.f,0.f},{0.f,0.f},{0.f,0.f},{0.f,0.f}};
    float2 accB[4] = {{0.f,0.f},{0.f,0.f},{0.f,0.f},{0.f,0.f}};

    for (int base = 0; base < cnt; base += 32) {
        int m = min(32, cnt - base);
        unsigned pk = 0;
        float val = 0.f;
        if (lane < m) {
            pk = g_epack[start + base + lane];
            val = g_dinv[pk & 0xFFFFu]
                * __half2float(__ushort_as_half((unsigned short)(pk >> 16)));
        }
        #pragma unroll 4
        for (int j = 0; j < m; j++) {
            unsigned p = __shfl_sync(0xffffffffu, pk, j);
            float nm = __shfl_sync(0xffffffffu, val, j) * dsn;
            int r = (int)(p & 0xFFFFu);
            const uint4* xp = (const uint4*)(g_xh + (size_t)r * DD) + lane;
            uint4 v0 = xp[0];
            uint4 v1 = xp[32];
            acc8(accA, v0, nm);
            acc8(accB, v1, nm);
        }
    }
    uint4 o0, o1;
    __half2* h0 = (__half2*)&o0;
    __half2* h1 = (__half2*)&o1;
    #pragma unroll
    for (int q = 0; q < 4; q++) {
        h0[q] = __float22half2_rn(accA[q]);
        h1[q] = __float22half2_rn(accB[q]);
    }
    uint4* op = (uint4*)(g_aggh + (size_t)n * DD) + lane;
    __stcs(op, o0);
    __stcs(op + 32, o1);
}

// ---------------- fp16 tensor-core GEMM: C = A @ W^T + bias ----------------
__device__ __forceinline__ void mma_f16(float* d, const unsigned* a, const unsigned* b) {
    asm volatile(
        "mma.sync.aligned.m16n8k16.row.col.f32.f16.f16.f32 "
        "{%0,%1,%2,%3}, {%4,%5,%6,%7}, {%8,%9}, {%0,%1,%2,%3};"
        : "+f"(d[0]), "+f"(d[1]), "+f"(d[2]), "+f"(d[3])
        : "r"(a[0]), "r"(a[1]), "r"(a[2]), "r"(a[3]), "r"(b[0]), "r"(b[1]));
}
__device__ __forceinline__ void cpa16(unsigned dst, const void* src, int sz) {
    asm volatile("cp.async.cg.shared.global [%0], [%1], 16, %2;"
                 :: "r"(dst), "l"(src), "r"(sz) : "memory");
}
__device__ __forceinline__ unsigned smem_u32(const void* p) {
    unsigned a;
    asm("{ .reg .u64 t; cvta.to.shared.u64 t, %1; cvt.u32.u64 %0, t; }" : "=r"(a) : "l"(p));
    return a;
}

#define KPH 40
#define ST_A (128 * KPH)
#define ST_B (256 * KPH)
#define STAGE_H (ST_A + ST_B)
#define GSMEM (3 * STAGE_H * 2)

__global__ __launch_bounds__(256, 1) void gemm_f16(const float* __restrict__ bias,
                                                   float* __restrict__ C,
                                                   int row0, int M) {
    extern __shared__ __half sm[];
    const unsigned smb = smem_u32(sm);

    const int tid  = threadIdx.x;
    const int lane = tid & 31;
    const int warp = tid >> 5;
    const int wm = warp & 1;
    const int wn = warp >> 1;
    const int g  = lane >> 2;
    const int tg = lane & 3;

    const int blockRow = row0 + blockIdx.y * 128;
    const int blockCol = blockIdx.x * 256;

    const int lr  = tid >> 1;
    const int c0h = (tid & 1) * 16;
    const int gr  = blockRow + lr;
    const int aSz = (gr < M) ? 16 : 0;
    const __half* aSrc = g_aggh + (size_t)min(gr, M - 1) * 512 + c0h;
    const __half* bSrc = g_wh + (size_t)(blockCol + tid) * 512;

    float acc[4][8][4];
    #pragma unroll
    for (int mt = 0; mt < 4; mt++)
        #pragma unroll
        for (int nt = 0; nt < 8; nt++)
            #pragma unroll
            for (int q = 0; q < 4; q++) acc[mt][nt][q] = 0.f;

    auto load_tile = [&](int s, int ch) {
        unsigned ab = smb + (unsigned)(s * STAGE_H) * 2;
        unsigned bb = ab + (unsigned)ST_A * 2;
        const __half* ap = aSrc + ch * 32;
        cpa16(ab + (lr * KPH + c0h) * 2, ap, aSz);
        cpa16(ab + (lr * KPH + c0h + 8) * 2, ap + 8, aSz);
        const __half* bp = bSrc + ch * 32;
        #pragma unroll
        for (int j = 0; j < 4; j++)
            cpa16(bb + (tid * KPH + j * 8) * 2, bp + j * 8, 16);
        asm volatile("cp.async.commit_group;" ::: "memory");
    };

    load_tile(0, 0);
    load_tile(1, 1);

    for (int ch = 0; ch < 16; ch++) {
        const int s = ch % 3;
        if (ch + 2 < 16) asm volatile("cp.async.wait_group 1;" ::: "memory");
        else             asm volatile("cp.async.wait_group 0;" ::: "memory");
        __syncthreads();
        if (ch + 2 < 16) load_tile((ch + 2) % 3, ch + 2);

        const __half* As = sm + s * STAGE_H;
        const __half* Bs = As + ST_A;

        #pragma unroll
        for (int ks = 0; ks < 32; ks += 16) {
            unsigned a[4][4], b[8][2];
            #pragma unroll
            for (int mt = 0; mt < 4; mt++) {
                int row = wm * 64 + mt * 16 + g;
                a[mt][0] = *(const unsigned*)&As[row * KPH + ks + tg * 2];
                a[mt][1] = *(const unsigned*)&As[(row + 8) * KPH + ks + tg * 2];
                a[mt][2] = *(const unsigned*)&As[row * KPH + ks + 8 + tg * 2];
                a[mt][3] = *(const unsigned*)&As[(row + 8) * KPH + ks + 8 + tg * 2];
            }
            #pragma unroll
            for (int nt = 0; nt < 8; nt++) {
                int col = wn * 64 + nt * 8 + g;
                b[nt][0] = *(const unsigned*)&Bs[col * KPH + ks + tg * 2];
                b[nt][1] = *(const unsigned*)&Bs[col * KPH + ks + 8 + tg * 2];
            }
            #pragma unroll
            for (int mt = 0; mt < 4; mt++)
                #pragma unroll
                for (int nt = 0; nt < 8; nt++)
                    mma_f16(acc[mt][nt], a[mt], b[nt]);
        }
        __syncthreads();
    }

    #pragma unroll
    for (int mt = 0; mt < 4; mt++) {
        int r0 = blockRow + wm * 64 + mt * 16 + g;
        #pragma unroll
        for (int nt = 0; nt < 8; nt++) {
            int col = blockCol + wn * 64 + nt * 8 + tg * 2;
            float b0 = bias[col], b1 = bias[col + 1];
            if (r0 < M) {
                float2 o = make_float2(acc[mt][nt][0] + b0, acc[mt][nt][1] + b1);
                *(float2*)(C + (size_t)r0 * 512 + col) = o;
            }
            if (r0 + 8 < M) {
                float2 o = make_float2(acc[mt][nt][2] + b0, acc[mt][nt][3] + b1);
                *(float2*)(C + (size_t)(r0 + 8) * 512 + col) = o;
            }
        }
    }
}

extern "C" void kernel_launch(void* const* d_in, const int* in_sizes, int n_in,
                              void* d_out, int out_size) {
    const float* x  = (const float*)d_in[0];
    const void*  ei = d_in[1];
    const float* ea = (const float*)d_in[2];
    const float* lw = (const float*)d_in[3];
    const float* lb = (const float*)d_in[4];
    const float* cw = (const float*)d_in[5];
    const float* cb = (const float*)d_in[6];
    float* out = (float*)d_out;

    cudaFuncSetAttribute(gemm_f16, cudaFuncAttributeMaxDynamicSharedMemorySize, GSMEM);

    int cur = -1;
    cudaGetDevice(&cur);
    const bool useStreams = g_sok && (cur == g_dev0);

    const int convGrid = (NN * DD / 8 + 255) / 256;
    const int aggGrid0 = NHALF / 8;                     // nodes [0, NHALF)
    const int aggGrid1 = (NN - NHALF + 7) / 8;          // nodes [NHALF, NN)
    dim3 gemmGrid0(2, NHALF / 128);
    dim3 gemmGrid1(2, (NN - NHALF + 127) / 128);

    if (useStreams) {
        // fork s1
        cudaEventRecord(g_evFork, 0);
        cudaStreamWaitEvent(g_s1, g_evFork, 0);
        // s1: convert
        prep_convert<<<convGrid, 256, 0, g_s1>>>(x, lw);
        cudaEventRecord(g_evConv, g_s1);

        // s0: edge chain
        prep_meta<<<(NN + 255) / 256, 256>>>(ei);
        edge_pass1<<<(EE + 255) / 256, 256>>>(ei, ea, cw, cb);
        scan_all<<<NBLK, SCAN_B>>>();
        fill_kernel<<<(EE + 255) / 256, 256>>>();
        cudaEventRecord(g_evFill, 0);

        // s0: agg half0 (needs conversions), then gemm half0
        cudaStreamWaitEvent(0, g_evConv, 0);
        agg_kernel<<<aggGrid0, 256>>>(0, NHALF);
        cudaEventRecord(g_evAgg0, 0);
        gemm_f16<<<gemmGrid0, 256, GSMEM>>>(lb, out, 0, NN);

        // s1: agg half1 after fill + agg0 (serialize the two LTS-bound aggs;
        // agg1 then co-runs with gemm0: LTS vs tensor pipe)
        cudaStreamWaitEvent(g_s1, g_evFill, 0);
        cudaStreamWaitEvent(g_s1, g_evAgg0, 0);
        agg_kernel<<<aggGrid1, 256, 0, g_s1>>>(NHALF, NN);
        gemm_f16<<<gemmGrid1, 256, GSMEM, g_s1>>>(lb, out, NHALF, NN);
        cudaEventRecord(g_evS1, g_s1);

        // join
        cudaStreamWaitEvent(0, g_evS1, 0);
    } else {
        prep_convert<<<convGrid, 256>>>(x, lw);
        prep_meta<<<(NN + 255) / 256, 256>>>(ei);
        edge_pass1<<<(EE + 255) / 256, 256>>>(ei, ea, cw, cb);
        scan_all<<<NBLK, SCAN_B>>>();
        fill_kernel<<<(EE + 255) / 256, 256>>>();
        agg_kernel<<<aggGrid0, 256>>>(0, NHALF);
        agg_kernel<<<aggGrid1, 256>>>(NHALF, NN);
        dim3 grid(2, (NN + 127) / 128);
        gemm_f16<<<grid, 256, GSMEM>>>(lb, out, 0, NN);
    }
}

// round 11
// speedup vs baseline: 1.0107x; 1.0107x over previous
#include <cuda_runtime.h>
#include <cuda_fp16.h>
#include <math.h>

#define NN 50000
#define EE 800000
#define DD 512

// ---------------- scratch (device globals; no allocations) ----------------
__device__ __align__(16) __half g_xh[(size_t)NN * DD];    // x in fp16
__device__ __align__(16) __half g_aggh[(size_t)NN * DD];  // aggregated, fp16
__device__ __align__(16) __half g_wh[512 * 512];          // W in fp16
__device__ __align__(16) float g_deg[NN];
__device__ __align__(16) float g_dinv[NN];
__device__ __align__(16) __half g_ew[EE];                 // edge confidence fp16
__device__ __align__(16) unsigned g_rc[EE];               // (col<<16)|row
__device__ int      g_cnt[NN];
__device__ int      g_off[NN];
__device__ int      g_cur[NN];
__device__ unsigned g_epack[EE];      // (ew_fp16 << 16) | src_row
__device__ unsigned g_tstate[128];    // lookback state
__device__ int      g_ticket;
__device__ int      g_idx64;

#define SCAN_B 512
#define NBLK   98

// ---------------- edge-index dtype-agnostic fetch ----------------
__device__ __forceinline__ long long edge_idx(const void* p, long long i) {
    if (g_idx64) return ((const long long*)p)[i];
    return (long long)((const int*)p)[i];
}

__device__ __forceinline__ uint4 cvt8(float4 f0, float4 f1) {
    uint4 o;
    __half2* oh = (__half2*)&o;
    oh[0] = __float22half2_rn(make_float2(f0.x, f0.y));
    oh[1] = __float22half2_rn(make_float2(f0.z, f0.w));
    oh[2] = __float22half2_rn(make_float2(f1.x, f1.y));
    oh[3] = __float22half2_rn(make_float2(f1.z, f1.w));
    return o;
}

// Convert x and W to fp16.
__global__ void prep_convert(const float* __restrict__ x, const float* __restrict__ W) {
    size_t i = (size_t)blockIdx.x * blockDim.x + threadIdx.x;
    if (i < 512 * 512 / 8)
        ((uint4*)g_wh)[i] = cvt8(((const float4*)W)[i * 2], ((const float4*)W)[i * 2 + 1]);
    if (i < (size_t)NN * DD / 8)
        ((uint4*)g_xh)[i] = cvt8(((const float4*)x)[i * 2], ((const float4*)x)[i * 2 + 1]);
}

// Edge-chain head: detect idx dtype, zero counters and scan state.
__global__ void prep_meta(const void* __restrict__ ei) {
    int i = blockIdx.x * blockDim.x + threadIdx.x;
    if (i == 0) {
        const long long* p = (const long long*)ei;
        int ok = 1;
        for (int j = 0; j < 64; j++) {
            long long v = p[j];
            if (v < 0 || v >= NN) { ok = 0; break; }
        }
        g_idx64 = ok;
        g_ticket = 0;
    }
    if (i < 128) g_tstate[i] = 0;
    if (i < NN) { g_deg[i] = 0.f; g_cnt[i] = 0; }
}

__global__ void edge_pass1(const void* __restrict__ ei,
                           const float* __restrict__ ea,
                           const float* __restrict__ cw,
                           const float* __restrict__ cb) {
    int e = blockIdx.x * blockDim.x + threadIdx.x;
    if (e >= EE) return;
    long long r = edge_idx(ei, e);
    long long c = edge_idx(ei, (long long)EE + e);
    atomicAdd(&g_deg[r], 1.0f);
    atomicAdd(&g_cnt[c], 1);
    g_rc[e] = ((unsigned)c << 16) | (unsigned)r;
    float z = ea[e * 3 + 0] * cw[0] + ea[e * 3 + 1] * cw[1]
            + ea[e * 3 + 2] * cw[2] + cb[0];
    g_ew[e] = __float2half(1.0f / (1.0f + expf(-z)));
}

// Single-launch decoupled-lookback scan; fuses node_dinv + cursor init.
__global__ __launch_bounds__(SCAN_B) void scan_all() {
    __shared__ int s[SCAN_B];
    __shared__ int sbid, sprev;
    const int tid = threadIdx.x;
    if (tid == 0) sbid = atomicAdd(&g_ticket, 1);
    __syncthreads();
    const int bid = sbid;
    const int i = bid * SCAN_B + tid;

    int v = (i < NN) ? g_cnt[i] : 0;
    if (i < NN) {
        float d = g_deg[i];
        g_dinv[i] = (d > 0.f) ? rsqrtf(d) : 0.f;
    }
    s[tid] = v;
    __syncthreads();
    for (int off = 1; off < SCAN_B; off <<= 1) {
        int t = (tid >= off) ? s[tid - off] : 0;
        __syncthreads();
        s[tid] += t;
        __syncthreads();
    }
    const int aggv = s[SCAN_B - 1];

    if (tid == 0) {
        if (bid == 0) {
            atomicExch(&g_tstate[0], (2u << 30) | (unsigned)aggv);
            sprev = 0;
        } else {
            atomicExch(&g_tstate[bid], (1u << 30) | (unsigned)aggv);
            int run = 0;
            for (int t = bid - 1; t >= 0; t--) {
                unsigned st;
                do { st = atomicOr(&g_tstate[t], 0u); } while ((st >> 30) == 0u);
                run += (int)(st & 0x3FFFFFFFu);
                if ((st >> 30) == 2u) break;
            }
            atomicExch(&g_tstate[bid], (2u << 30) | (unsigned)(run + aggv));
            sprev = run;
        }
    }
    __syncthreads();
    if (i < NN) {
        int off = sprev + s[tid] - v;
        g_off[i] = off;
        g_cur[i] = off;
    }
}

// Fill CSR payload from packed rc.
__global__ void fill_kernel() {
    int e = blockIdx.x * blockDim.x + threadIdx.x;
    if (e >= EE) return;
    unsigned rc = g_rc[e];
    unsigned ew = (unsigned)__half_as_ushort(g_ew[e]);
    int p = atomicAdd(&g_cur[rc >> 16], 1);
    g_epack[p] = (ew << 16) | (rc & 0xFFFFu);
}

__device__ __forceinline__ void acc8(float2* acc, uint4 v, float nm) {
    const __half2* h = (const __half2*)&v;
    #pragma unroll
    for (int q = 0; q < 4; q++) {
        float2 f = __half22float2(h[q]);
        acc[q].x += f.x * nm;
        acc[q].y += f.y * nm;
    }
}

// Gather aggregation: one WARP per node, batch-level software pipelining —
// next epack batch + dinv lookup prefetched while current batch gathers.
__global__ __launch_bounds__(256) void agg_kernel() {
    int warp = threadIdx.x >> 5;
    int lane = threadIdx.x & 31;
    int n = blockIdx.x * 8 + warp;
    if (n >= NN) return;
    int start = g_off[n];
    int cnt   = g_cnt[n];
    float dsn = g_dinv[n];

    float2 accA[4] = {{0.f,0.f},{0.f,0.f},{0.f,0.f},{0.f,0.f}};
    float2 accB[4] = {{0.f,0.f},{0.f,0.f},{0.f,0.f},{0.f,0.f}};

    unsigned pk = 0;
    if (lane < cnt) pk = g_epack[start + lane];

    for (int base = 0; base < cnt; base += 32) {
        int m = min(32, cnt - base);
        float val = 0.f;
        if (lane < m)
            val = g_dinv[pk & 0xFFFFu]
                * __half2float(__ushort_as_half((unsigned short)(pk >> 16)));
        unsigned pkc = pk;
        // prefetch next batch (overlaps the gather loop below)
        pk = 0;
        if (base + 32 + lane < cnt) pk = g_epack[start + base + 32 + lane];

        #pragma unroll 4
        for (int j = 0; j < m; j++) {
            unsigned p = __shfl_sync(0xffffffffu, pkc, j);
            float nm = __shfl_sync(0xffffffffu, val, j) * dsn;
            int r = (int)(p & 0xFFFFu);
            const uint4* xp = (const uint4*)(g_xh + (size_t)r * DD) + lane;
            uint4 v0 = xp[0];
            uint4 v1 = xp[32];
            acc8(accA, v0, nm);
            acc8(accB, v1, nm);
        }
    }
    uint4 o0, o1;
    __half2* h0 = (__half2*)&o0;
    __half2* h1 = (__half2*)&o1;
    #pragma unroll
    for (int q = 0; q < 4; q++) {
        h0[q] = __float22half2_rn(accA[q]);
        h1[q] = __float22half2_rn(accB[q]);
    }
    uint4* op = (uint4*)(g_aggh + (size_t)n * DD) + lane;
    __stcs(op, o0);
    __stcs(op + 32, o1);
}

// ---------------- fp16 tensor-core GEMM: C = A @ W^T + bias ----------------
__device__ __forceinline__ void mma_f16(float* d, const unsigned* a, const unsigned* b) {
    asm volatile(
        "mma.sync.aligned.m16n8k16.row.col.f32.f16.f16.f32 "
        "{%0,%1,%2,%3}, {%4,%5,%6,%7}, {%8,%9}, {%0,%1,%2,%3};"
        : "+f"(d[0]), "+f"(d[1]), "+f"(d[2]), "+f"(d[3])
        : "r"(a[0]), "r"(a[1]), "r"(a[2]), "r"(a[3]), "r"(b[0]), "r"(b[1]));
}
__device__ __forceinline__ void ldm_x4(unsigned& r0, unsigned& r1,
                                       unsigned& r2, unsigned& r3, unsigned addr) {
    asm volatile("ldmatrix.sync.aligned.m8n8.x4.shared.b16 {%0,%1,%2,%3}, [%4];"
                 : "=r"(r0), "=r"(r1), "=r"(r2), "=r"(r3) : "r"(addr));
}
__device__ __forceinline__ void cpa16(unsigned dst, const void* src, int sz) {
    asm volatile("cp.async.cg.shared.global [%0], [%1], 16, %2;"
                 :: "r"(dst), "l"(src), "r"(sz) : "memory");
}
__device__ __forceinline__ unsigned smem_u32(const void* p) {
    unsigned a;
    asm("{ .reg .u64 t; cvta.to.shared.u64 t, %1; cvt.u32.u64 %0, t; }" : "=r"(a) : "l"(p));
    return a;
}

#define KPH 40
#define ST_A (128 * KPH)
#define ST_B (256 * KPH)
#define STAGE_H (ST_A + ST_B)
#define GSMEM (3 * STAGE_H * 2)

__global__ __launch_bounds__(256, 1) void gemm_f16(const float* __restrict__ bias,
                                                   float* __restrict__ C,
                                                   int M) {
    extern __shared__ __half sm[];
    const unsigned smb = smem_u32(sm);

    const int tid  = threadIdx.x;
    const int lane = tid & 31;
    const int warp = tid >> 5;
    const int wm = warp & 1;
    const int wn = warp >> 1;
    const int g  = lane >> 2;
    const int tg = lane & 3;

    const int blockRow = blockIdx.y * 128;
    const int blockCol = blockIdx.x * 256;

    // ldmatrix per-lane address components
    const int aRowOff = (lane & 7) + ((lane >> 3) & 1) * 8;  // 0..15
    const int aKOff   = (lane >> 4) * 8;                     // 0/8
    const int bColOff = (lane & 7);
    const int bKOff   = ((lane >> 3) & 1) * 8;               // 0/8
    const int bNtHalf = (lane >> 4);                         // 0/1

    const int lr  = tid >> 1;
    const int c0h = (tid & 1) * 16;
    const int gr  = blockRow + lr;
    const int aSz = (gr < M) ? 16 : 0;
    const __half* aSrc = g_aggh + (size_t)min(gr, M - 1) * 512 + c0h;
    const __half* bSrc = g_wh + (size_t)(blockCol + tid) * 512;

    float acc[4][8][4];
    #pragma unroll
    for (int mt = 0; mt < 4; mt++)
        #pragma unroll
        for (int nt = 0; nt < 8; nt++)
            #pragma unroll
            for (int q = 0; q < 4; q++) acc[mt][nt][q] = 0.f;

    auto load_tile = [&](int s, int ch) {
        unsigned ab = smb + (unsigned)(s * STAGE_H) * 2;
        unsigned bb = ab + (unsigned)ST_A * 2;
        const __half* ap = aSrc + ch * 32;
        cpa16(ab + (lr * KPH + c0h) * 2, ap, aSz);
        cpa16(ab + (lr * KPH + c0h + 8) * 2, ap + 8, aSz);
        const __half* bp = bSrc + ch * 32;
        #pragma unroll
        for (int j = 0; j < 4; j++)
            cpa16(bb + (tid * KPH + j * 8) * 2, bp + j * 8, 16);
        asm volatile("cp.async.commit_group;" ::: "memory");
    };

    load_tile(0, 0);
    load_tile(1, 1);

    for (int ch = 0; ch < 16; ch++) {
        const int s = ch % 3;
        if (ch + 2 < 16) asm volatile("cp.async.wait_group 1;" ::: "memory");
        else             asm volatile("cp.async.wait_group 0;" ::: "memory");
        __syncthreads();
        if (ch + 2 < 16) load_tile((ch + 2) % 3, ch + 2);

        const unsigned asb = smb + (unsigned)(s * STAGE_H) * 2;
        const unsigned bsb = asb + (unsigned)ST_A * 2;

        #pragma unroll
        for (int ks = 0; ks < 32; ks += 16) {
            unsigned a[4][4], bf[8][2];
            #pragma unroll
            for (int mt = 0; mt < 4; mt++) {
                unsigned addr = asb + (unsigned)(((wm * 64 + mt * 16 + aRowOff) * KPH
                                                 + ks + aKOff) * 2);
                ldm_x4(a[mt][0], a[mt][1], a[mt][2], a[mt][3], addr);
            }
            #pragma unroll
            for (int q = 0; q < 4; q++) {
                int col = wn * 64 + (2 * q + bNtHalf) * 8 + bColOff;
                unsigned addr = bsb + (unsigned)((col * KPH + ks + bKOff) * 2);
                unsigned r0, r1, r2, r3;
                ldm_x4(r0, r1, r2, r3, addr);
                bf[2 * q][0] = r0; bf[2 * q][1] = r1;
                bf[2 * q + 1][0] = r2; bf[2 * q + 1][1] = r3;
            }
            #pragma unroll
            for (int mt = 0; mt < 4; mt++)
                #pragma unroll
                for (int nt = 0; nt < 8; nt++)
                    mma_f16(acc[mt][nt], a[mt], bf[nt]);
        }
        __syncthreads();
    }

    #pragma unroll
    for (int mt = 0; mt < 4; mt++) {
        int r0 = blockRow + wm * 64 + mt * 16 + g;
        #pragma unroll
        for (int nt = 0; nt < 8; nt++) {
            int col = blockCol + wn * 64 + nt * 8 + tg * 2;
            float b0 = bias[col], b1 = bias[col + 1];
            if (r0 < M) {
                float2 o = make_float2(acc[mt][nt][0] + b0, acc[mt][nt][1] + b1);
                *(float2*)(C + (size_t)r0 * 512 + col) = o;
            }
            if (r0 + 8 < M) {
                float2 o = make_float2(acc[mt][nt][2] + b0, acc[mt][nt][3] + b1);
                *(float2*)(C + (size_t)(r0 + 8) * 512 + col) = o;
            }
        }
    }
}

extern "C" void kernel_launch(void* const* d_in, const int* in_sizes, int n_in,
                              void* d_out, int out_size) {
    const float* x  = (const float*)d_in[0];
    const void*  ei = d_in[1];
    const float* ea = (const float*)d_in[2];
    const float* lw = (const float*)d_in[3];
    const float* lb = (const float*)d_in[4];
    const float* cw = (const float*)d_in[5];
    const float* cb = (const float*)d_in[6];
    float* out = (float*)d_out;

    cudaFuncSetAttribute(gemm_f16, cudaFuncAttributeMaxDynamicSharedMemorySize, GSMEM);

    prep_convert<<<(NN * DD / 8 + 255) / 256, 256>>>(x, lw);
    prep_meta<<<(NN + 255) / 256, 256>>>(ei);
    edge_pass1<<<(EE + 255) / 256, 256>>>(ei, ea, cw, cb);
    scan_all<<<NBLK, SCAN_B>>>();
    fill_kernel<<<(EE + 255) / 256, 256>>>();
    agg_kernel<<<(NN + 7) / 8, 256>>>();

    dim3 grid(2, (NN + 127) / 128);
    gemm_f16<<<grid, 256, GSMEM>>>(lb, out, NN);
}